// round 11
// baseline (speedup 1.0000x reference)
#include <cuda_runtime.h>
#include <cuda_fp16.h>
#include <cstdint>

#define NN 50000
#define NN_PAD 50048                         // 391 * 128 (M-tile padded)
#define NE 800000
#define CC 64
#define SCALE_F (2.0f / 3.0f)
#define DIAGW (SCALE_F - 1.0f)
#define SCAN_B 1024
#define NBLK ((NN + SCAN_B - 1) / SCAN_B)   // 49
#define MASK48 0xFFFFFFFFFFFFULL
#define MTILES 391                           // ceil(NN/128)

// ---------------- static device scratch (zero-init at load; calls restore) ----------
__device__ unsigned long long g_deg64[2][NN]; // packed {cnt:16, wsum:48 fixed 2^-32}
__device__ unsigned g_agg[2][NBLK];
__device__ float g_dis[2][NN];
__device__ int   g_rowptr[2][NN + 1];
__device__ int   g_cursor[2][NN];
__device__ __align__(16) uint2  g_edges[2][NE];
__device__ __align__(16) float  g_T[2][4][(size_t)NN * CC];      // fp32 Tx1..Tx4
__device__ __align__(16) __half g_Th[2][4][(size_t)NN_PAD * CC]; // fp16 shadows Tx1..Tx4
__device__ __align__(16) __half g_xh[(size_t)NN_PAD * CC];       // fp16 shadow of x
__device__ __align__(16) __half g_Wh[2][5][64 * 64];             // W^T fp16: [n][k]

__device__ __forceinline__ uint32_t smem_u32(const void* p) {
    uint32_t a;
    asm("{ .reg .u64 t; cvta.to.shared.u64 t, %1; cvt.u32.u64 %0, t; }" : "=r"(a) : "l"(p));
    return a;
}

// ---------------- launch 0: degree atomics + fp16 shadow of x + W->fp16 transpose ----
__global__ void k_degcount_xh(const int* __restrict__ ei,
                              const float* __restrict__ ew,
                              const float* __restrict__ x,
                              const float* __restrict__ W1,
                              const float* __restrict__ W2) {
    int e = blockIdx.x * blockDim.x + threadIdx.x;
    if (e < 2 * 5 * 4096) {  // transpose W into fp16 [dir][chunk][n][k]
        int dir = e / 20480;
        int rem = e % 20480;
        int c = rem / 4096;
        int kk = (rem % 4096) / 64;
        int n  = rem % 64;
        const float* W = dir ? W2 : W1;
        g_Wh[dir][c][n * 64 + kk] = __float2half_rn(W[c * 4096 + kk * 64 + n]);
    }
    if (e >= NE) return;
    int a = ei[e];
    int b = ei[NE + e];
    float w = ew[e];
    unsigned long long pv = (1ULL << 48) + (unsigned long long)(w * 4294967296.0f);
    atomicAdd(&g_deg64[0][a], pv);
    atomicAdd(&g_deg64[1][b], pv);
    float2 f0 = ((const float2*)x)[e];
    ((__half2*)g_xh)[e] = __float22half2_rn(f0);
    float2 f1 = ((const float2*)x)[e + NE];
    ((__half2*)g_xh)[e + NE] = __float22half2_rn(f1);
}

// ---------------- launch 1: single-pass scan (decoupled lookback) + rsqrt ------------
__global__ void __launch_bounds__(SCAN_B) k_scan_fused() {
    int dir = blockIdx.y;
    __shared__ int wsum[32];
    __shared__ int s_boff;
    int tid = threadIdx.x;
    int lane = tid & 31, wid = tid >> 5;
    int i = blockIdx.x * SCAN_B + tid;
    int v = 0;
    if (i < NN) {
        unsigned long long p = g_deg64[dir][i];
        g_deg64[dir][i] = 0ULL;
        v = (int)(p >> 48);
        float deg = (float)(p & MASK48) * 2.3283064365386963e-10f;
        g_dis[dir][i] = (deg > 0.f) ? rsqrtf(deg) : 0.f;
    }
    int xv = v;
    #pragma unroll
    for (int o = 1; o < 32; o <<= 1) {
        int t = __shfl_up_sync(0xffffffffu, xv, o);
        if (lane >= o) xv += t;
    }
    if (lane == 31) wsum[wid] = xv;
    __syncthreads();
    if (wid == 0) {
        int s = wsum[lane];
        #pragma unroll
        for (int o = 1; o < 32; o <<= 1) {
            int t = __shfl_up_sync(0xffffffffu, s, o);
            if (lane >= o) s += t;
        }
        wsum[lane] = s;
    }
    __syncthreads();
    int incl = xv + ((wid > 0) ? wsum[wid - 1] : 0);
    int total = wsum[31];
    if (tid == 0) atomicExch(&g_agg[dir][blockIdx.x], 0x80000000u | (unsigned)total);
    if (wid == 0) {
        int s = 0;
        for (int o = lane + 1; o <= (int)blockIdx.x; o += 32) {
            unsigned a;
            do { a = *(volatile unsigned*)&g_agg[dir][blockIdx.x - o]; }
            while (!(a & 0x80000000u));
            s += (int)(a & 0x7FFFFFFFu);
        }
        #pragma unroll
        for (int o2 = 16; o2 > 0; o2 >>= 1) s += __shfl_down_sync(0xffffffffu, s, o2);
        if (lane == 0) s_boff = s;
    }
    __syncthreads();
    int boff = s_boff;
    if (i < NN) {
        int r = (incl - v) + boff;
        g_rowptr[dir][i] = r;
        g_cursor[dir][i] = r;
    }
    if (blockIdx.x == 0 && tid == 0) g_rowptr[dir][NN] = NE;
}

// ---------------- launch 2: scatter edges into both CSRs (+ re-zero g_agg) -----------
__global__ void k_scatter(const int* __restrict__ ei,
                          const float* __restrict__ ew) {
    int e = blockIdx.x * blockDim.x + threadIdx.x;
    if (e < 2 * NBLK) ((unsigned*)g_agg)[e] = 0;
    if (e >= NE) return;
    int a = ei[e];
    int b = ei[NE + e];
    float w = ew[e];
    float d0a = g_dis[0][a], d0b = g_dis[0][b];
    float d1a = g_dis[1][a], d1b = g_dis[1][b];
    float w0 = -SCALE_F * d0a * w * d0b;
    float w1 = -SCALE_F * d1b * w * d1a;
    int p0 = atomicAdd(&g_cursor[0][a], 1);
    g_edges[0][p0] = make_uint2((unsigned)b, __float_as_uint(w0));
    int p1 = atomicAdd(&g_cursor[1][b], 1);
    g_edges[1][p1] = make_uint2((unsigned)a, __float_as_uint(w1));
}

// ---------------- SpMV: y = alpha*(diag_w*v + A vh) + beta*prev ----------------------
// 16 lanes/node, 4ch/lane. uint4 edge loads (2 edges each, peel for alignment).
__global__ void __launch_bounds__(256) k_spmv(const float* __restrict__ x,
                                              int vsel, int psel, int ysel,
                                              float alpha, float beta, int writeF) {
    int dir = blockIdx.y;
    int node = blockIdx.x * 16 + (threadIdx.x >> 4);
    int lane16 = threadIdx.x & 15;
    if (node >= NN) return;
    const float*  __restrict__ v  = (vsel < 0) ? x : g_T[dir][vsel];
    const __half* __restrict__ vh = (vsel < 0) ? g_xh : g_Th[dir][vsel];
    const uint2* __restrict__ ed = g_edges[dir];
    int s = g_rowptr[dir][node];
    int e = g_rowptr[dir][node + 1];
    int c4 = lane16 * 4;
    float a0 = 0.f, a1 = 0.f, a2 = 0.f, a3 = 0.f;
    int j = s;
    if (j < e && (j & 1)) {   // peel to 16B alignment
        uint2 e0 = __ldg(&ed[j]);
        uint2 g0 = *(const uint2*)(vh + (size_t)e0.x * CC + c4);
        float w = __uint_as_float(e0.y);
        float2 f0 = __half22float2(*(const __half2*)&g0.x);
        float2 f1 = __half22float2(*(const __half2*)&g0.y);
        a0 = fmaf(w, f0.x, a0); a1 = fmaf(w, f0.y, a1);
        a2 = fmaf(w, f1.x, a2); a3 = fmaf(w, f1.y, a3);
        ++j;
    }
    for (; j + 8 <= e; j += 8) {
        uint4 q0 = __ldg((const uint4*)&ed[j]);
        uint4 q1 = __ldg((const uint4*)&ed[j + 2]);
        uint4 q2 = __ldg((const uint4*)&ed[j + 4]);
        uint4 q3 = __ldg((const uint4*)&ed[j + 6]);
        uint2 gh[8];
        gh[0] = *(const uint2*)(vh + (size_t)q0.x * CC + c4);
        gh[1] = *(const uint2*)(vh + (size_t)q0.z * CC + c4);
        gh[2] = *(const uint2*)(vh + (size_t)q1.x * CC + c4);
        gh[3] = *(const uint2*)(vh + (size_t)q1.z * CC + c4);
        gh[4] = *(const uint2*)(vh + (size_t)q2.x * CC + c4);
        gh[5] = *(const uint2*)(vh + (size_t)q2.z * CC + c4);
        gh[6] = *(const uint2*)(vh + (size_t)q3.x * CC + c4);
        gh[7] = *(const uint2*)(vh + (size_t)q3.z * CC + c4);
        unsigned wb[8] = {q0.y, q0.w, q1.y, q1.w, q2.y, q2.w, q3.y, q3.w};
        #pragma unroll
        for (int q = 0; q < 8; ++q) {
            float w = __uint_as_float(wb[q]);
            float2 f0 = __half22float2(*(const __half2*)&gh[q].x);
            float2 f1 = __half22float2(*(const __half2*)&gh[q].y);
            a0 = fmaf(w, f0.x, a0);
            a1 = fmaf(w, f0.y, a1);
            a2 = fmaf(w, f1.x, a2);
            a3 = fmaf(w, f1.y, a3);
        }
    }
    for (; j < e; ++j) {
        uint2 e0 = __ldg(&ed[j]);
        uint2 g0 = *(const uint2*)(vh + (size_t)e0.x * CC + c4);
        float w = __uint_as_float(e0.y);
        float2 f0 = __half22float2(*(const __half2*)&g0.x);
        float2 f1 = __half22float2(*(const __half2*)&g0.y);
        a0 = fmaf(w, f0.x, a0);
        a1 = fmaf(w, f0.y, a1);
        a2 = fmaf(w, f1.x, a2);
        a3 = fmaf(w, f1.y, a3);
    }
    float4 vm = *(const float4*)(v + (size_t)node * CC + c4);
    float r0 = alpha * fmaf(DIAGW, vm.x, a0);
    float r1 = alpha * fmaf(DIAGW, vm.y, a1);
    float r2 = alpha * fmaf(DIAGW, vm.z, a2);
    float r3 = alpha * fmaf(DIAGW, vm.w, a3);
    if (beta != 0.f) {
        const float* __restrict__ p = (psel < 0) ? x : g_T[dir][psel];
        float4 pm = *(const float4*)(p + (size_t)node * CC + c4);
        r0 = fmaf(beta, pm.x, r0);
        r1 = fmaf(beta, pm.y, r1);
        r2 = fmaf(beta, pm.z, r2);
        r3 = fmaf(beta, pm.w, r3);
    }
    if (writeF) {
        float* __restrict__ y = g_T[dir][ysel];
        *(float4*)(y + (size_t)node * CC + c4) = make_float4(r0, r1, r2, r3);
    }
    __half* __restrict__ yh = g_Th[dir][ysel];
    __half2 h0 = __floats2half2_rn(r0, r1);
    __half2 h1 = __floats2half2_rn(r2, r3);
    uint2 packed;
    packed.x = *(const unsigned*)&h0;
    packed.y = *(const unsigned*)&h1;
    *(uint2*)(yh + (size_t)node * CC + c4) = packed;
}

// ---------------- HMMA GEMM (R8 single-buffer version, proven) -----------------------
// grid (MTILES, 2), 256 threads (8 warps). Warp w owns rows [w*16, w*16+16).
#define APAD 72   // 144B row stride -> 16B rotation/row -> conflict-free ldmatrix
__global__ void __launch_bounds__(256) k_gemm_tc(const float* __restrict__ b1,
                                                 const float* __restrict__ b2,
                                                 float* __restrict__ out) {
    __shared__ __half sA[128][APAD];
    __shared__ __half sB[64][APAD];
    int dir = blockIdx.y;
    int tid = threadIdx.x;
    int wid = tid >> 5, lane = tid & 31;
    int n0 = blockIdx.x * 128;

    float acc[8][4];
    #pragma unroll
    for (int t = 0; t < 8; ++t)
        #pragma unroll
        for (int q = 0; q < 4; ++q) acc[t][q] = 0.f;

    for (int c = 0; c < 5; ++c) {
        const __half* __restrict__ Asrc = (c == 0) ? g_xh : g_Th[dir][c - 1];
        const __half* __restrict__ Bsrc = g_Wh[dir][c];
        __syncthreads();
        // A: 128 rows x 64 halves = 1024 x 16B
        #pragma unroll
        for (int it = 0; it < 4; ++it) {
            int idx = tid + it * 256;
            int row = idx >> 3, seg = idx & 7;
            uint4 val = *(const uint4*)(Asrc + (size_t)(n0 + row) * CC + seg * 8);
            *(uint4*)(&sA[row][seg * 8]) = val;
        }
        // B: 64 rows x 64 halves = 512 x 16B
        #pragma unroll
        for (int it = 0; it < 2; ++it) {
            int idx = tid + it * 256;
            int row = idx >> 3, seg = idx & 7;
            uint4 val = *(const uint4*)(Bsrc + row * 64 + seg * 8);
            *(uint4*)(&sB[row][seg * 8]) = val;
        }
        __syncthreads();
        int row0 = wid * 16;
        #pragma unroll
        for (int kk = 0; kk < 4; ++kk) {
            int k0 = kk * 16;
            uint32_t a0, a1, a2, a3;
            {
                uint32_t addr = smem_u32(&sA[row0 + (lane & 15)][k0 + ((lane >> 4) << 3)]);
                asm volatile("ldmatrix.sync.aligned.m8n8.x4.shared.b16 {%0,%1,%2,%3}, [%4];"
                             : "=r"(a0), "=r"(a1), "=r"(a2), "=r"(a3) : "r"(addr));
            }
            #pragma unroll
            for (int nt2 = 0; nt2 < 4; ++nt2) {
                int nb = nt2 * 16;
                uint32_t b0, b1, b2, b3;
                {
                    int nrow = nb + ((lane >> 4) << 3) + (lane & 7);
                    int kh = k0 + (((lane >> 3) & 1) << 3);
                    uint32_t addr = smem_u32(&sB[nrow][kh]);
                    asm volatile("ldmatrix.sync.aligned.m8n8.x4.shared.b16 {%0,%1,%2,%3}, [%4];"
                                 : "=r"(b0), "=r"(b1), "=r"(b2), "=r"(b3) : "r"(addr));
                }
                asm volatile(
                    "mma.sync.aligned.m16n8k16.row.col.f32.f16.f16.f32 "
                    "{%0,%1,%2,%3}, {%4,%5,%6,%7}, {%8,%9}, {%0,%1,%2,%3};"
                    : "+f"(acc[nt2 * 2][0]), "+f"(acc[nt2 * 2][1]),
                      "+f"(acc[nt2 * 2][2]), "+f"(acc[nt2 * 2][3])
                    : "r"(a0), "r"(a1), "r"(a2), "r"(a3), "r"(b0), "r"(b1));
                asm volatile(
                    "mma.sync.aligned.m16n8k16.row.col.f32.f16.f16.f32 "
                    "{%0,%1,%2,%3}, {%4,%5,%6,%7}, {%8,%9}, {%0,%1,%2,%3};"
                    : "+f"(acc[nt2 * 2 + 1][0]), "+f"(acc[nt2 * 2 + 1][1]),
                      "+f"(acc[nt2 * 2 + 1][2]), "+f"(acc[nt2 * 2 + 1][3])
                    : "r"(a0), "r"(a1), "r"(a2), "r"(a3), "r"(b2), "r"(b3));
            }
        }
    }
    // epilogue
    const float* __restrict__ bias = dir ? b2 : b1;
    int rA = n0 + wid * 16 + (lane >> 2);
    int cbase = (lane & 3) * 2;
    #pragma unroll
    for (int nt = 0; nt < 8; ++nt) {
        int col = nt * 8 + cbase;
        float bx = __ldg(bias + col), by = __ldg(bias + col + 1);
        if (rA < NN) {
            float* o = out + (size_t)rA * 128 + dir * 64 + col;
            o[0] = acc[nt][0] + bx;
            o[1] = acc[nt][1] + by;
        }
        if (rA + 8 < NN) {
            float* o = out + (size_t)(rA + 8) * 128 + dir * 64 + col;
            o[0] = acc[nt][2] + bx;
            o[1] = acc[nt][3] + by;
        }
    }
}

// ---------------- launch ----------------
extern "C" void kernel_launch(void* const* d_in, const int* in_sizes, int n_in,
                              void* d_out, int out_size) {
    const float* x  = (const float*)d_in[0];
    const int*   ei = (const int*)d_in[1];
    const float* ew = (const float*)d_in[2];
    const float* W1 = (const float*)d_in[3];
    const float* b1 = (const float*)d_in[4];
    const float* W2 = (const float*)d_in[5];
    const float* b2 = (const float*)d_in[6];
    float*       out = (float*)d_out;

    (void)in_sizes; (void)n_in; (void)out_size;

    const int TB = 256;
    k_degcount_xh<<<(NE + TB - 1) / TB, TB>>>(ei, ew, x, W1, W2);
    k_scan_fused<<<dim3(NBLK, 2), SCAN_B>>>();
    k_scatter<<<(NE + TB - 1) / TB, TB>>>(ei, ew);

    const dim3 SPMV_G((NN + 15) / 16, 2);
    k_spmv<<<SPMV_G, TB>>>(x, -1, -1, 0, 1.0f,  0.0f, 1);  // Tx1
    k_spmv<<<SPMV_G, TB>>>(x,  0, -1, 1, 2.0f, -1.0f, 1);  // Tx2
    k_spmv<<<SPMV_G, TB>>>(x,  1,  0, 2, 2.0f, -1.0f, 1);  // Tx3
    k_spmv<<<SPMV_G, TB>>>(x,  2,  1, 3, 2.0f, -1.0f, 0);  // Tx4 (fp16 shadow only)
    k_gemm_tc<<<dim3(MTILES, 2), 256>>>(b1, b2, out);
}

// round 12
// speedup vs baseline: 1.1155x; 1.1155x over previous
#include <cuda_runtime.h>
#include <cuda_fp16.h>
#include <cstdint>

#define NN 50000
#define NN_PAD 50048                         // 391 * 128 (M-tile padded)
#define NE 800000
#define CC 64
#define SCALE_F (2.0f / 3.0f)
#define DIAGW (SCALE_F - 1.0f)
#define SCAN_B 1024
#define NBLK ((NN + SCAN_B - 1) / SCAN_B)   // 49
#define MASK48 0xFFFFFFFFFFFFULL
#define MTILES 391                           // ceil(NN/128)

// ---------------- static device scratch (zero-init at load; calls restore) ----------
__device__ unsigned long long g_deg64[2][NN]; // packed {cnt:16, wsum:48 fixed 2^-32}
__device__ unsigned g_agg[2][NBLK];
__device__ float g_dis[2][NN];
__device__ int   g_rowptr[2][NN + 1];
__device__ int   g_cursor[2][NN];
__device__ __align__(16) uint2  g_edges[2][NE];
__device__ __align__(16) float  g_T[2][4][(size_t)NN * CC];      // fp32 Tx1..Tx4
__device__ __align__(16) __half g_Th[2][4][(size_t)NN_PAD * CC]; // fp16 shadows Tx1..Tx4
__device__ __align__(16) __half g_xh[(size_t)NN_PAD * CC];       // fp16 shadow of x
__device__ __align__(16) __half g_Wh[2][5][64 * 64];             // W^T fp16: [n][k]

__device__ __forceinline__ uint32_t smem_u32(const void* p) {
    uint32_t a;
    asm("{ .reg .u64 t; cvta.to.shared.u64 t, %1; cvt.u32.u64 %0, t; }" : "=r"(a) : "l"(p));
    return a;
}
#define CP_ASYNC16(dst, src) \
    asm volatile("cp.async.ca.shared.global [%0], [%1], 16;" :: "r"(dst), "l"(src))
#define CP_COMMIT() asm volatile("cp.async.commit_group;" ::: "memory")
#define CP_WAIT1()  asm volatile("cp.async.wait_group 1;" ::: "memory")
#define CP_WAIT0()  asm volatile("cp.async.wait_group 0;" ::: "memory")

// ---------------- launch 0: degree atomics + fp16 shadow of x + W->fp16 transpose ----
__global__ void k_degcount_xh(const int* __restrict__ ei,
                              const float* __restrict__ ew,
                              const float* __restrict__ x,
                              const float* __restrict__ W1,
                              const float* __restrict__ W2) {
    int e = blockIdx.x * blockDim.x + threadIdx.x;
    if (e < 2 * 5 * 4096) {  // transpose W into fp16 [dir][chunk][n][k]
        int dir = e / 20480;
        int rem = e % 20480;
        int c = rem / 4096;
        int kk = (rem % 4096) / 64;
        int n  = rem % 64;
        const float* W = dir ? W2 : W1;
        g_Wh[dir][c][n * 64 + kk] = __float2half_rn(W[c * 4096 + kk * 64 + n]);
    }
    if (e >= NE) return;
    int a = ei[e];
    int b = ei[NE + e];
    float w = ew[e];
    unsigned long long pv = (1ULL << 48) + (unsigned long long)(w * 4294967296.0f);
    atomicAdd(&g_deg64[0][a], pv);
    atomicAdd(&g_deg64[1][b], pv);
    float2 f0 = ((const float2*)x)[e];
    ((__half2*)g_xh)[e] = __float22half2_rn(f0);
    float2 f1 = ((const float2*)x)[e + NE];
    ((__half2*)g_xh)[e + NE] = __float22half2_rn(f1);
}

// ---------------- launch 1: single-pass scan (decoupled lookback) + rsqrt ------------
__global__ void __launch_bounds__(SCAN_B) k_scan_fused() {
    int dir = blockIdx.y;
    __shared__ int wsum[32];
    __shared__ int s_boff;
    int tid = threadIdx.x;
    int lane = tid & 31, wid = tid >> 5;
    int i = blockIdx.x * SCAN_B + tid;
    int v = 0;
    if (i < NN) {
        unsigned long long p = g_deg64[dir][i];
        g_deg64[dir][i] = 0ULL;
        v = (int)(p >> 48);
        float deg = (float)(p & MASK48) * 2.3283064365386963e-10f;
        g_dis[dir][i] = (deg > 0.f) ? rsqrtf(deg) : 0.f;
    }
    int xv = v;
    #pragma unroll
    for (int o = 1; o < 32; o <<= 1) {
        int t = __shfl_up_sync(0xffffffffu, xv, o);
        if (lane >= o) xv += t;
    }
    if (lane == 31) wsum[wid] = xv;
    __syncthreads();
    if (wid == 0) {
        int s = wsum[lane];
        #pragma unroll
        for (int o = 1; o < 32; o <<= 1) {
            int t = __shfl_up_sync(0xffffffffu, s, o);
            if (lane >= o) s += t;
        }
        wsum[lane] = s;
    }
    __syncthreads();
    int incl = xv + ((wid > 0) ? wsum[wid - 1] : 0);
    int total = wsum[31];
    if (tid == 0) atomicExch(&g_agg[dir][blockIdx.x], 0x80000000u | (unsigned)total);
    if (wid == 0) {
        int s = 0;
        for (int o = lane + 1; o <= (int)blockIdx.x; o += 32) {
            unsigned a;
            do { a = *(volatile unsigned*)&g_agg[dir][blockIdx.x - o]; }
            while (!(a & 0x80000000u));
            s += (int)(a & 0x7FFFFFFFu);
        }
        #pragma unroll
        for (int o2 = 16; o2 > 0; o2 >>= 1) s += __shfl_down_sync(0xffffffffu, s, o2);
        if (lane == 0) s_boff = s;
    }
    __syncthreads();
    int boff = s_boff;
    if (i < NN) {
        int r = (incl - v) + boff;
        g_rowptr[dir][i] = r;
        g_cursor[dir][i] = r;
    }
    if (blockIdx.x == 0 && tid == 0) g_rowptr[dir][NN] = NE;
}

// ---------------- launch 2: scatter edges into both CSRs (+ re-zero g_agg) -----------
__global__ void k_scatter(const int* __restrict__ ei,
                          const float* __restrict__ ew) {
    int e = blockIdx.x * blockDim.x + threadIdx.x;
    if (e < 2 * NBLK) ((unsigned*)g_agg)[e] = 0;
    if (e >= NE) return;
    int a = ei[e];
    int b = ei[NE + e];
    float w = ew[e];
    float d0a = g_dis[0][a], d0b = g_dis[0][b];
    float d1a = g_dis[1][a], d1b = g_dis[1][b];
    float w0 = -SCALE_F * d0a * w * d0b;
    float w1 = -SCALE_F * d1b * w * d1a;
    int p0 = atomicAdd(&g_cursor[0][a], 1);
    g_edges[0][p0] = make_uint2((unsigned)b, __float_as_uint(w0));
    int p1 = atomicAdd(&g_cursor[1][b], 1);
    g_edges[1][p1] = make_uint2((unsigned)a, __float_as_uint(w1));
}

// ---------------- SpMV (R8 loop verbatim; only the fp32 store is predicated) ---------
__global__ void __launch_bounds__(256) k_spmv(const float* __restrict__ x,
                                              int vsel, int psel, int ysel,
                                              float alpha, float beta, int writeF) {
    int dir = blockIdx.y;
    int node = blockIdx.x * 16 + (threadIdx.x >> 4);
    int lane16 = threadIdx.x & 15;
    if (node >= NN) return;
    const float*  __restrict__ v  = (vsel < 0) ? x : g_T[dir][vsel];
    const __half* __restrict__ vh = (vsel < 0) ? g_xh : g_Th[dir][vsel];
    const uint2* __restrict__ ed = g_edges[dir];
    int s = g_rowptr[dir][node];
    int e = g_rowptr[dir][node + 1];
    int c4 = lane16 * 4;
    float a0 = 0.f, a1 = 0.f, a2 = 0.f, a3 = 0.f;
    int j = s;
    for (; j + 8 <= e; j += 8) {
        uint2 ee[8];
        #pragma unroll
        for (int q = 0; q < 8; ++q) ee[q] = __ldg(&ed[j + q]);
        uint2 gh[8];
        #pragma unroll
        for (int q = 0; q < 8; ++q)
            gh[q] = *(const uint2*)(vh + (size_t)ee[q].x * CC + c4);
        #pragma unroll
        for (int q = 0; q < 8; ++q) {
            float w = __uint_as_float(ee[q].y);
            float2 f0 = __half22float2(*(const __half2*)&gh[q].x);
            float2 f1 = __half22float2(*(const __half2*)&gh[q].y);
            a0 = fmaf(w, f0.x, a0);
            a1 = fmaf(w, f0.y, a1);
            a2 = fmaf(w, f1.x, a2);
            a3 = fmaf(w, f1.y, a3);
        }
    }
    for (; j < e; ++j) {
        uint2 e0 = __ldg(&ed[j]);
        uint2 g0 = *(const uint2*)(vh + (size_t)e0.x * CC + c4);
        float w = __uint_as_float(e0.y);
        float2 f0 = __half22float2(*(const __half2*)&g0.x);
        float2 f1 = __half22float2(*(const __half2*)&g0.y);
        a0 = fmaf(w, f0.x, a0);
        a1 = fmaf(w, f0.y, a1);
        a2 = fmaf(w, f1.x, a2);
        a3 = fmaf(w, f1.y, a3);
    }
    float4 vm = *(const float4*)(v + (size_t)node * CC + c4);
    float r0 = alpha * fmaf(DIAGW, vm.x, a0);
    float r1 = alpha * fmaf(DIAGW, vm.y, a1);
    float r2 = alpha * fmaf(DIAGW, vm.z, a2);
    float r3 = alpha * fmaf(DIAGW, vm.w, a3);
    if (beta != 0.f) {
        const float* __restrict__ p = (psel < 0) ? x : g_T[dir][psel];
        float4 pm = *(const float4*)(p + (size_t)node * CC + c4);
        r0 = fmaf(beta, pm.x, r0);
        r1 = fmaf(beta, pm.y, r1);
        r2 = fmaf(beta, pm.z, r2);
        r3 = fmaf(beta, pm.w, r3);
    }
    if (writeF) {
        float* __restrict__ y = g_T[dir][ysel];
        *(float4*)(y + (size_t)node * CC + c4) = make_float4(r0, r1, r2, r3);
    }
    __half* __restrict__ yh = g_Th[dir][ysel];
    __half2 h0 = __floats2half2_rn(r0, r1);
    __half2 h1 = __floats2half2_rn(r2, r3);
    uint2 packed;
    packed.x = *(const unsigned*)&h0;
    packed.y = *(const unsigned*)&h1;
    *(uint2*)(yh + (size_t)node * CC + c4) = packed;
}

// ---------------- HMMA GEMM, cp.async double-buffered in DYNAMIC smem ----------------
// grid (MTILES, 2), 256 threads (8 warps). Stage: A[128][72] + B[64][72] halves.
#define APAD 72                        // 144B row stride -> conflict-free ldmatrix
#define STAGE_HALVES ((128 + 64) * APAD)   // 13824 halves = 27648 B
#define GEMM_SMEM (2 * STAGE_HALVES * 2)   // 55296 B
__global__ void __launch_bounds__(256) k_gemm_tc(const float* __restrict__ b1,
                                                 const float* __restrict__ b2,
                                                 float* __restrict__ out) {
    extern __shared__ __half dynsmem[];
    int dir = blockIdx.y;
    int tid = threadIdx.x;
    int wid = tid >> 5, lane = tid & 31;
    int n0 = blockIdx.x * 128;

    float acc[8][4];
    #pragma unroll
    for (int t = 0; t < 8; ++t)
        #pragma unroll
        for (int q = 0; q < 4; ++q) acc[t][q] = 0.f;

    int lrow = tid >> 3, lseg = tid & 7;   // 256 threads -> 32 rows x 8 segs per pass

    #define SA_ROW(s, r)  (dynsmem + (s) * STAGE_HALVES + (r) * APAD)
    #define SB_ROW(s, r)  (dynsmem + (s) * STAGE_HALVES + 128 * APAD + (r) * APAD)

    #define LOAD_CHUNK(buf, c) do {                                              \
        const __half* Asrc_ = ((c) == 0) ? g_xh : g_Th[dir][(c) - 1];            \
        _Pragma("unroll")                                                        \
        for (int it = 0; it < 4; ++it) {                                         \
            int row = lrow + it * 32;                                            \
            CP_ASYNC16(smem_u32(SA_ROW(buf, row) + lseg * 8),                    \
                       Asrc_ + (size_t)(n0 + row) * CC + lseg * 8);              \
        }                                                                        \
        const __half* Bsrc_ = g_Wh[dir][c];                                      \
        _Pragma("unroll")                                                        \
        for (int it = 0; it < 2; ++it) {                                         \
            int row = lrow + it * 32;                                            \
            CP_ASYNC16(smem_u32(SB_ROW(buf, row) + lseg * 8),                    \
                       Bsrc_ + row * 64 + lseg * 8);                             \
        }                                                                        \
        CP_COMMIT();                                                             \
    } while (0)

    LOAD_CHUNK(0, 0);
    #pragma unroll
    for (int c = 0; c < 5; ++c) {
        int buf = c & 1;
        if (c < 4) LOAD_CHUNK(buf ^ 1, c + 1);
        if (c < 4) CP_WAIT1(); else CP_WAIT0();
        __syncthreads();
        int row0 = wid * 16;
        #pragma unroll
        for (int kk = 0; kk < 4; ++kk) {
            int k0 = kk * 16;
            uint32_t a0, a1, a2, a3;
            {
                uint32_t addr = smem_u32(SA_ROW(buf, row0 + (lane & 15)) + k0 + ((lane >> 4) << 3));
                asm volatile("ldmatrix.sync.aligned.m8n8.x4.shared.b16 {%0,%1,%2,%3}, [%4];"
                             : "=r"(a0), "=r"(a1), "=r"(a2), "=r"(a3) : "r"(addr));
            }
            #pragma unroll
            for (int nt2 = 0; nt2 < 4; ++nt2) {
                int nb = nt2 * 16;
                uint32_t b0, b1, b2, b3;
                {
                    int nrow = nb + ((lane >> 4) << 3) + (lane & 7);
                    int kh = k0 + (((lane >> 3) & 1) << 3);
                    uint32_t addr = smem_u32(SB_ROW(buf, nrow) + kh);
                    asm volatile("ldmatrix.sync.aligned.m8n8.x4.shared.b16 {%0,%1,%2,%3}, [%4];"
                                 : "=r"(b0), "=r"(b1), "=r"(b2), "=r"(b3) : "r"(addr));
                }
                asm volatile(
                    "mma.sync.aligned.m16n8k16.row.col.f32.f16.f16.f32 "
                    "{%0,%1,%2,%3}, {%4,%5,%6,%7}, {%8,%9}, {%0,%1,%2,%3};"
                    : "+f"(acc[nt2 * 2][0]), "+f"(acc[nt2 * 2][1]),
                      "+f"(acc[nt2 * 2][2]), "+f"(acc[nt2 * 2][3])
                    : "r"(a0), "r"(a1), "r"(a2), "r"(a3), "r"(b0), "r"(b1));
                asm volatile(
                    "mma.sync.aligned.m16n8k16.row.col.f32.f16.f16.f32 "
                    "{%0,%1,%2,%3}, {%4,%5,%6,%7}, {%8,%9}, {%0,%1,%2,%3};"
                    : "+f"(acc[nt2 * 2 + 1][0]), "+f"(acc[nt2 * 2 + 1][1]),
                      "+f"(acc[nt2 * 2 + 1][2]), "+f"(acc[nt2 * 2 + 1][3])
                    : "r"(a0), "r"(a1), "r"(a2), "r"(a3), "r"(b2), "r"(b3));
            }
        }
        __syncthreads();
    }
    // epilogue
    const float* __restrict__ bias = dir ? b2 : b1;
    int rA = n0 + wid * 16 + (lane >> 2);
    int cbase = (lane & 3) * 2;
    #pragma unroll
    for (int nt = 0; nt < 8; ++nt) {
        int col = nt * 8 + cbase;
        float bx = __ldg(bias + col), by = __ldg(bias + col + 1);
        if (rA < NN) {
            float* o = out + (size_t)rA * 128 + dir * 64 + col;
            o[0] = acc[nt][0] + bx;
            o[1] = acc[nt][1] + by;
        }
        if (rA + 8 < NN) {
            float* o = out + (size_t)(rA + 8) * 128 + dir * 64 + col;
            o[0] = acc[nt][2] + bx;
            o[1] = acc[nt][3] + by;
        }
    }
}

// ---------------- launch ----------------
extern "C" void kernel_launch(void* const* d_in, const int* in_sizes, int n_in,
                              void* d_out, int out_size) {
    const float* x  = (const float*)d_in[0];
    const int*   ei = (const int*)d_in[1];
    const float* ew = (const float*)d_in[2];
    const float* W1 = (const float*)d_in[3];
    const float* b1 = (const float*)d_in[4];
    const float* W2 = (const float*)d_in[5];
    const float* b2 = (const float*)d_in[6];
    float*       out = (float*)d_out;

    (void)in_sizes; (void)n_in; (void)out_size;

    // idempotent; first (uncaptured) correctness call sets it, persists thereafter
    cudaFuncSetAttribute(k_gemm_tc, cudaFuncAttributeMaxDynamicSharedMemorySize, GEMM_SMEM);

    const int TB = 256;
    k_degcount_xh<<<(NE + TB - 1) / TB, TB>>>(ei, ew, x, W1, W2);
    k_scan_fused<<<dim3(NBLK, 2), SCAN_B>>>();
    k_scatter<<<(NE + TB - 1) / TB, TB>>>(ei, ew);

    const dim3 SPMV_G((NN + 15) / 16, 2);
    k_spmv<<<SPMV_G, TB>>>(x, -1, -1, 0, 1.0f,  0.0f, 1);  // Tx1
    k_spmv<<<SPMV_G, TB>>>(x,  0, -1, 1, 2.0f, -1.0f, 1);  // Tx2
    k_spmv<<<SPMV_G, TB>>>(x,  1,  0, 2, 2.0f, -1.0f, 1);  // Tx3
    k_spmv<<<SPMV_G, TB>>>(x,  2,  1, 3, 2.0f, -1.0f, 0);  // Tx4 (fp16 shadow only)
    k_gemm_tc<<<dim3(MTILES, 2), 256, GEMM_SMEM>>>(b1, b2, out);
}